// round 9
// baseline (speedup 1.0000x reference)
#include <cuda_runtime.h>
#include <cuda_bf16.h>
#include <math.h>

#define NN 50000
#define EE 800000
#define BB 64
#define OBSD 128
#define MHD 256
#define NAD 16

// ---------------- scratch ----------------
__device__ float          g_x[NN * 128];
__device__ __nv_bfloat16  g_h[NN * 128];
__device__ float g_as_a[NN * 2];
__device__ float g_ad_a[NN * 2];
__device__ float g_es_a[NN * 2];
__device__ float g_as_b[NN * 2];
__device__ float g_ad_b[NN * 2];
__device__ float g_es_b[NN * 2];
__device__ float g_wf0[4 * 8];
__device__ float g_wf1[4 * 128];
__device__ float g_wf2[2 * 128];
__device__ int   g_deg[NN + 1];
__device__ int   g_off[NN + 1];
__device__ int   g_cur[NN];
__device__ int   g_csr[EE];
__device__ float g_pool[BB * 64];
__device__ float g_cnt[BB];

__device__ __forceinline__ float lrelu(float v) { return v > 0.f ? v : 0.2f * v; }

__device__ __forceinline__ void red4(float* p, float a, float b, float c, float d) {
    asm volatile("red.global.add.v4.f32 [%0], {%1,%2,%3,%4};"
                 :: "l"(p), "f"(a), "f"(b), "f"(c), "f"(d) : "memory");
}

// ---- packed f32x2 helpers ----
__device__ __forceinline__ unsigned long long pack2(float x, float y) {
    unsigned long long r;
    asm("mov.b64 %0, {%1, %2};" : "=l"(r) : "r"(__float_as_uint(x)), "r"(__float_as_uint(y)));
    return r;
}
__device__ __forceinline__ void unpack2(unsigned long long v, float& x, float& y) {
    unsigned lo, hi;
    asm("mov.b64 {%0, %1}, %2;" : "=r"(lo), "=r"(hi) : "l"(v));
    x = __uint_as_float(lo); y = __uint_as_float(hi);
}
__device__ __forceinline__ void fma2(unsigned long long& d, unsigned long long a, unsigned long long b) {
    asm("fma.rn.f32x2 %0, %1, %2, %0;" : "+l"(d) : "l"(a), "l"(b));
}

// bf16 helpers
__device__ __forceinline__ void st_h4(__nv_bfloat16* p, const float* f) {
    uint2 u;
    *reinterpret_cast<__nv_bfloat162*>(&u.x) = __floats2bfloat162_rn(f[0], f[1]);
    *reinterpret_cast<__nv_bfloat162*>(&u.y) = __floats2bfloat162_rn(f[2], f[3]);
    *reinterpret_cast<uint2*>(p) = u;
}
__device__ __forceinline__ void st_h2(__nv_bfloat16* p, const float* f) {
    unsigned u;
    *reinterpret_cast<__nv_bfloat162*>(&u) = __floats2bfloat162_rn(f[0], f[1]);
    *reinterpret_cast<unsigned*>(p) = u;
}
__device__ __forceinline__ void acc_h4(float* acc, unsigned ux, unsigned uy, float w) {
    float2 lo = __bfloat1622float2(*reinterpret_cast<__nv_bfloat162*>(&ux));
    float2 hi = __bfloat1622float2(*reinterpret_cast<__nv_bfloat162*>(&uy));
    acc[0] += w * lo.x; acc[1] += w * lo.y; acc[2] += w * hi.x; acc[3] += w * hi.y;
}
__device__ __forceinline__ void acc_h2(float* acc, unsigned u, float w) {
    float2 lo = __bfloat1622float2(*reinterpret_cast<__nv_bfloat162*>(&u));
    acc[0] += w * lo.x; acc[1] += w * lo.y;
}

// =================== k_init: folds (warp-per-dot) + zero scratch ===================
__global__ void k_init(const float* __restrict__ W0, const float* __restrict__ as0, const float* __restrict__ ad0,
                       const float* __restrict__ W1, const float* __restrict__ as1, const float* __restrict__ ad1,
                       const float* __restrict__ W2, const float* __restrict__ as2, const float* __restrict__ ad2) {
    int bid = blockIdx.x;
    int tid = threadIdx.x;
    if (bid < 100) {
        int wj = bid * 8 + (tid >> 5);      // 0..799
        int lane = tid & 31;
        const float* av; const float* Wp; float* outp;
        if (wj < 32) {
            int a = wj / 8, kk = wj % 8, h = a & 1;
            av = ((a < 2) ? as0 : ad0) + h * 64;
            Wp = W0 + kk * 128 + h * 64;
            outp = &g_wf0[a * 8 + kk];
        } else if (wj < 544) {
            int i = wj - 32, a = i / 128, kk = i % 128, h = a & 1;
            av = ((a < 2) ? as1 : ad1) + h * 64;
            Wp = W1 + kk * 128 + h * 64;
            outp = &g_wf1[a * 128 + kk];
        } else {
            int i = wj - 544, a = i / 128, kk = i % 128;
            av = (a < 1) ? as2 : ad2;
            Wp = W2 + kk * 64;
            outp = &g_wf2[a * 128 + kk];
        }
        float s = Wp[lane] * av[lane] + Wp[lane + 32] * av[lane + 32];
#pragma unroll
        for (int o = 16; o > 0; o >>= 1) s += __shfl_down_sync(0xffffffffu, s, o);
        if (lane == 0) *outp = s;
    } else {
        const int TOT = (NN + 1) + BB * 64 + BB;
        for (int i = (bid - 100) * 256 + tid; i < TOT; i += 60 * 256) {
            if (i <= NN)                g_deg[i] = 0;
            else if (i <= NN + BB * 64) g_pool[i - NN - 1] = 0.f;
            else                        g_cnt[i - NN - 1 - BB * 64] = 0.f;
        }
    }
}

// =================== CSR build ===================
__global__ void k_hist(const int* __restrict__ ei) {
    const int4* d4 = reinterpret_cast<const int4*>(ei + EE);
    for (int i = blockIdx.x * blockDim.x + threadIdx.x; i < EE / 4; i += gridDim.x * blockDim.x) {
        int4 v = d4[i];
        atomicAdd(&g_deg[v.x], 1);
        atomicAdd(&g_deg[v.y], 1);
        atomicAdd(&g_deg[v.z], 1);
        atomicAdd(&g_deg[v.w], 1);
    }
}
__global__ void k_scan() {
    __shared__ int sh[1024];
    const int PER = 49;
    int tid = threadIdx.x;
    int base = tid * PER;
    int s = 0;
    for (int k = 0; k < PER; k++) {
        int i = base + k;
        if (i < NN) s += g_deg[i];
    }
    sh[tid] = s;
    __syncthreads();
    for (int o = 1; o < 1024; o <<= 1) {
        int t = (tid >= o) ? sh[tid - o] : 0;
        __syncthreads();
        sh[tid] += t;
        __syncthreads();
    }
    int run = sh[tid] - s;
    for (int k = 0; k < PER; k++) {
        int i = base + k;
        if (i < NN) {
            int d = g_deg[i];
            g_off[i] = run;
            g_cur[i] = run;
            run += d;
        }
    }
    if (tid == 0) g_off[NN] = EE;
}

// =================== fused: CSR fill + layer-0 GEMM (independent work) ===================
#define G0B 782
__global__ void k_fillg0(const int* __restrict__ ei,
                         const float* __restrict__ xin, const float* __restrict__ W) {
    __shared__ float Wsh[8 * 128];
    __shared__ float wfsh[32];
    int tid = threadIdx.x;
    if (blockIdx.x < G0B) {
        // ---- gemm0 ----
        int lane = tid & 31, wp = tid >> 5;
        for (int i = tid; i < 8 * 128; i += 256) Wsh[i] = W[i];
        if (tid < 32) wfsh[tid] = g_wf0[tid];
        __syncthreads();

        for (int node = blockIdx.x * 8 + wp; node < NN; node += G0B * 8) {
            float4 xa = *reinterpret_cast<const float4*>(&xin[node * 8]);
            float4 xb = *reinterpret_cast<const float4*>(&xin[node * 8 + 4]);
            float xk[8] = {xa.x, xa.y, xa.z, xa.w, xb.x, xb.y, xb.z, xb.w};
            float acc[4] = {0.f, 0.f, 0.f, 0.f};
#pragma unroll
            for (int k = 0; k < 8; k++) {
                float4 w = *reinterpret_cast<const float4*>(&Wsh[k * 128 + lane * 4]);
                acc[0] += xk[k] * w.x; acc[1] += xk[k] * w.y;
                acc[2] += xk[k] * w.z; acc[3] += xk[k] * w.w;
            }
            st_h4(&g_h[(size_t)node * 128 + lane * 4], acc);

            int a = lane & 3;
            float s = 0.f;
#pragma unroll
            for (int k = 0; k < 8; k++) s += xk[k] * wfsh[a * 8 + k];
            float other = __shfl_down_sync(0xffffffffu, s, 2);
            if (lane < 2) {
                g_as_a[node * 2 + lane] = s;
                g_es_a[node * 2 + lane] = lrelu(s + other);
            } else if (lane < 4) {
                g_ad_a[node * 2 + lane - 2] = s;
            }
        }
    } else {
        // ---- CSR fill ----
        const int4* s4 = reinterpret_cast<const int4*>(ei);
        const int4* d4 = reinterpret_cast<const int4*>(ei + EE);
        for (int i = (blockIdx.x - G0B) * 256 + tid; i < EE / 4; i += G0B * 256) {
            int4 s = s4[i];
            int4 d = d4[i];
            g_csr[atomicAdd(&g_cur[d.x], 1)] = s.x;
            g_csr[atomicAdd(&g_cur[d.y], 1)] = s.y;
            g_csr[atomicAdd(&g_cur[d.z], 1)] = s.z;
            g_csr[atomicAdd(&g_cur[d.w], 1)] = s.w;
        }
    }
}

// =================== big GEMM (128 -> HC) with packed f32x2 ===================
template <int HC>
__global__ void __launch_bounds__(256) k_gemm128(const float* __restrict__ W) {
    constexpr int VEC = HC / 32;
    constexpr int P   = VEC / 2;
    constexpr int KT  = 32;
    constexpr int NCH = 64;
    __shared__ float Wsh[KT * HC];
    __shared__ unsigned long long xsh2[NCH * KT];
    int tid = threadIdx.x, lane = tid & 31, wp = tid >> 5;

    for (int base = blockIdx.x * NCH; base < NN; base += gridDim.x * NCH) {
        unsigned long long acc2[8][P];
#pragma unroll
        for (int n = 0; n < 8; n++)
#pragma unroll
            for (int p = 0; p < P; p++) acc2[n][p] = 0ull;

        for (int k0 = 0; k0 < 128; k0 += KT) {
            for (int i = tid; i < KT * HC; i += 256)
                Wsh[i] = W[((i / HC) + k0) * HC + (i % HC)];
            for (int i = tid; i < NCH * KT; i += 256) {
                int n = base + i / KT;
                float x = (n < NN) ? g_x[(size_t)n * 128 + k0 + (i % KT)] : 0.f;
                xsh2[i] = pack2(x, x);
            }
            __syncthreads();
#pragma unroll
            for (int kk = 0; kk < KT; kk += 4) {
                unsigned long long wv2[4][P];
#pragma unroll
                for (int j = 0; j < 4; j++)
#pragma unroll
                    for (int p = 0; p < P; p++)
                        wv2[j][p] = *reinterpret_cast<const unsigned long long*>(
                            &Wsh[(kk + j) * HC + lane * VEC + 2 * p]);
#pragma unroll
                for (int n = 0; n < 8; n++) {
                    ulonglong2 xa = *reinterpret_cast<const ulonglong2*>(&xsh2[(wp * 8 + n) * KT + kk]);
                    ulonglong2 xb = *reinterpret_cast<const ulonglong2*>(&xsh2[(wp * 8 + n) * KT + kk + 2]);
#pragma unroll
                    for (int p = 0; p < P; p++) {
                        fma2(acc2[n][p], xa.x, wv2[0][p]);
                        fma2(acc2[n][p], xa.y, wv2[1][p]);
                        fma2(acc2[n][p], xb.x, wv2[2][p]);
                        fma2(acc2[n][p], xb.y, wv2[3][p]);
                    }
                }
            }
            __syncthreads();
        }

#pragma unroll
        for (int n = 0; n < 8; n++) {
            int node = base + wp * 8 + n;
            if (node >= NN) break;
            float f[VEC];
#pragma unroll
            for (int p = 0; p < P; p++) unpack2(acc2[n][p], f[2 * p], f[2 * p + 1]);
            if (VEC == 4) st_h4(&g_h[(size_t)node * HC + lane * 4], f);
            else          st_h2(&g_h[(size_t)node * HC + lane * 2], f);
        }
    }
}

// =================== fused softmax-aggregate + next-layer alpha (+optional pool) ===================
template <int HC, int H, bool ACT, int NA, bool POOL>
__global__ void __launch_bounds__(256) k_agg(const float* __restrict__ bias,
                                             const float* __restrict__ aS,
                                             const float* __restrict__ aD,
                                             const float* __restrict__ eS,
                                             float* __restrict__ nS,
                                             float* __restrict__ nD,
                                             float* __restrict__ nE,
                                             const float* __restrict__ wfn,
                                             const int* __restrict__ batch) {
    constexpr int VEC = HC / 32;
    __shared__ int   s_s[8][32];
    __shared__ float s_w[8][32 * H];
    int lane = threadIdx.x & 31, wp = threadIdx.x >> 5;
    int node = blockIdx.x * 8 + wp;
    if (node >= NN) return;
    int head = (H == 2) ? (lane >> 4) : 0;

    float wfa[(NA > 0) ? NA : 1][VEC];
    if (NA > 0) {
#pragma unroll
        for (int a = 0; a < NA; a++)
#pragma unroll
            for (int v = 0; v < VEC; v++)
                wfa[a][v] = wfn[a * 128 + lane * VEC + v];
    }

    float ad0 = aD[node * H];
    float ad1 = (H == 2) ? aD[node * H + 1] : 0.f;
    int beg = g_off[node], end = g_off[node + 1];

    float acc[VEC];
#pragma unroll
    for (int v = 0; v < VEC; v++) acc[v] = 0.f;
    float d0 = 0.f, d1 = 0.f;

    const __nv_bfloat16* __restrict__ hbase = g_h;

    for (int chunk = beg; chunk < end; chunk += 32) {
        int i = chunk + lane;
        if (i < end) {
            int s = g_csr[i];
            s_s[wp][lane] = s;
            if (H == 2) {
                float2 a = *reinterpret_cast<const float2*>(&aS[s * 2]);
                float w0 = expf(lrelu(a.x + ad0));
                float w1 = expf(lrelu(a.y + ad1));
                d0 += w0; d1 += w1;
                s_w[wp][lane * 2]     = w0;
                s_w[wp][lane * 2 + 1] = w1;
            } else {
                float w0 = expf(lrelu(aS[s] + ad0));
                d0 += w0;
                s_w[wp][lane] = w0;
            }
        }
        __syncwarp();
        int cnt = min(32, end - chunk);
        int j = 0;
        for (; j + 8 <= cnt; j += 8) {
            int   ss[8];
            float ww[8];
#pragma unroll
            for (int u = 0; u < 8; u++) {
                ss[u] = s_s[wp][j + u];
                ww[u] = (H == 2) ? s_w[wp][(j + u) * 2 + head] : s_w[wp][j + u];
            }
            if (VEC == 4) {
                uint2 hv[8];
#pragma unroll
                for (int u = 0; u < 8; u++)
                    hv[u] = *reinterpret_cast<const uint2*>(&hbase[(size_t)ss[u] * HC + lane * 4]);
#pragma unroll
                for (int u = 0; u < 8; u++) acc_h4(acc, hv[u].x, hv[u].y, ww[u]);
            } else {
                unsigned hv[8];
#pragma unroll
                for (int u = 0; u < 8; u++)
                    hv[u] = *reinterpret_cast<const unsigned*>(&hbase[(size_t)ss[u] * HC + lane * 2]);
#pragma unroll
                for (int u = 0; u < 8; u++) acc_h2(acc, hv[u], ww[u]);
            }
        }
        for (; j + 4 <= cnt; j += 4) {
            int   ss[4];
            float ww[4];
#pragma unroll
            for (int u = 0; u < 4; u++) {
                ss[u] = s_s[wp][j + u];
                ww[u] = (H == 2) ? s_w[wp][(j + u) * 2 + head] : s_w[wp][j + u];
            }
            if (VEC == 4) {
                uint2 hv[4];
#pragma unroll
                for (int u = 0; u < 4; u++)
                    hv[u] = *reinterpret_cast<const uint2*>(&hbase[(size_t)ss[u] * HC + lane * 4]);
#pragma unroll
                for (int u = 0; u < 4; u++) acc_h4(acc, hv[u].x, hv[u].y, ww[u]);
            } else {
                unsigned hv[4];
#pragma unroll
                for (int u = 0; u < 4; u++)
                    hv[u] = *reinterpret_cast<const unsigned*>(&hbase[(size_t)ss[u] * HC + lane * 2]);
#pragma unroll
                for (int u = 0; u < 4; u++) acc_h2(acc, hv[u], ww[u]);
            }
        }
        for (; j < cnt; j++) {
            int s   = s_s[wp][j];
            float w = (H == 2) ? s_w[wp][j * 2 + head] : s_w[wp][j];
            if (VEC == 4) {
                uint2 hv = *reinterpret_cast<const uint2*>(&hbase[(size_t)s * HC + lane * 4]);
                acc_h4(acc, hv.x, hv.y, w);
            } else {
                unsigned hv = *reinterpret_cast<const unsigned*>(&hbase[(size_t)s * HC + lane * 2]);
                acc_h2(acc, hv, w);
            }
        }
        __syncwarp();
    }

    // self loop
    float ws = expf(eS[node * H + head]);
    if (VEC == 4) {
        uint2 hv = *reinterpret_cast<const uint2*>(&hbase[(size_t)node * HC + lane * 4]);
        acc_h4(acc, hv.x, hv.y, ws);
    } else {
        unsigned hv = *reinterpret_cast<const unsigned*>(&hbase[(size_t)node * HC + lane * 2]);
        acc_h2(acc, hv, ws);
    }

#pragma unroll
    for (int o = 16; o > 0; o >>= 1) {
        d0 += __shfl_xor_sync(0xffffffffu, d0, o);
        if (H == 2) d1 += __shfl_xor_sync(0xffffffffu, d1, o);
    }
    float dh = (H == 2 && head) ? d1 : d0;
    float inv = 1.0f / (dh + ws + 1e-16f);

    float outv[VEC];
#pragma unroll
    for (int v = 0; v < VEC; v++) {
        float t = acc[v] * inv + bias[lane * VEC + v];
        if (ACT) t = t > 0.f ? t : expm1f(t);
        outv[v] = t;
    }

    if (POOL) {
        // fused global-mean-pool accumulation (VEC==2 path: layer 2)
        int b = batch[node];
        float o2 = __shfl_down_sync(0xffffffffu, outv[0], 1);
        float o3 = __shfl_down_sync(0xffffffffu, outv[VEC - 1], 1);
        if ((lane & 1) == 0)
            red4(&g_pool[b * 64 + lane * 2], outv[0], outv[VEC - 1], o2, o3);
        if (lane == 0) atomicAdd(&g_cnt[b], 1.0f);
    } else {
        if (VEC == 4)
            *reinterpret_cast<float4*>(&g_x[(size_t)node * HC + lane * 4]) =
                make_float4(outv[0], outv[1], outv[2], outv[3]);
        else
            *reinterpret_cast<float2*>(&g_x[(size_t)node * HC + lane * 2]) =
                make_float2(outv[0], outv[1]);
    }

    // next-layer alpha from outv
    if (NA > 0) {
        float dots[(NA > 0) ? NA : 1];
#pragma unroll
        for (int a = 0; a < NA; a++) {
            float p = 0.f;
#pragma unroll
            for (int v = 0; v < VEC; v++) p += outv[v] * wfa[a][v];
#pragma unroll
            for (int o = 16; o > 0; o >>= 1) p += __shfl_xor_sync(0xffffffffu, p, o);
            dots[a] = p;
        }
        if (lane == 0) {
            constexpr int Hn = NA / 2;
#pragma unroll
            for (int h = 0; h < Hn; h++) {
                nS[node * Hn + h] = dots[h];
                nD[node * Hn + h] = dots[Hn + h];
                nE[node * Hn + h] = lrelu(dots[h] + dots[Hn + h]);
            }
        }
    }
}

// =================== MLP head ===================
__global__ void k_mlp(const float* __restrict__ obs,
                      const float* __restrict__ Ws1, const float* __restrict__ bs1,
                      const float* __restrict__ lng, const float* __restrict__ lnb,
                      const float* __restrict__ Ws2, const float* __restrict__ bs2,
                      const float* __restrict__ Wa,  const float* __restrict__ ba,
                      const float* __restrict__ Wc,  const float* __restrict__ bc,
                      float* __restrict__ out) {
    __shared__ float comb[64 + OBSD];
    __shared__ float hb[MHD];
    __shared__ float h2[MHD];
    __shared__ float rb[8];
    __shared__ float stats[2];

    int b = blockIdx.x;
    int tid = threadIdx.x;

    if (tid < 64)             comb[tid] = g_pool[b * 64 + tid] / fmaxf(g_cnt[b], 1.0f);
    else if (tid < 64 + OBSD) comb[tid] = obs[b * OBSD + (tid - 64)];
    __syncthreads();

    float s = bs1[tid];
    for (int k = 0; k < 64 + OBSD; k++) s += comb[k] * Ws1[k * MHD + tid];

    float v = s;
#pragma unroll
    for (int o = 16; o > 0; o >>= 1) v += __shfl_down_sync(0xffffffffu, v, o);
    if ((tid & 31) == 0) rb[tid >> 5] = v;
    __syncthreads();
    if (tid == 0) { float t = 0.f; for (int w = 0; w < 8; w++) t += rb[w]; stats[0] = t / MHD; }
    __syncthreads();
    float mu = stats[0];
    float dv = s - mu;
    v = dv * dv;
#pragma unroll
    for (int o = 16; o > 0; o >>= 1) v += __shfl_down_sync(0xffffffffu, v, o);
    if ((tid & 31) == 0) rb[tid >> 5] = v;
    __syncthreads();
    if (tid == 0) { float t = 0.f; for (int w = 0; w < 8; w++) t += rb[w]; stats[1] = t / MHD; }
    __syncthreads();

    float hn = dv * rsqrtf(stats[1] + 1e-5f) * lng[tid] + lnb[tid];
    hb[tid] = fmaxf(hn, 0.f);
    __syncthreads();

    float s2 = bs2[tid];
    for (int k = 0; k < MHD; k++) s2 += hb[k] * Ws2[k * MHD + tid];
    h2[tid] = fmaxf(s2, 0.f);
    __syncthreads();

    if (tid < NAD) {
        float t = ba[tid];
        for (int k = 0; k < MHD; k++) t += h2[k] * Wa[k * NAD + tid];
        out[b * NAD + tid] = t;
    }
    if (tid == NAD) {
        float t = bc[0];
        for (int k = 0; k < MHD; k++) t += h2[k] * Wc[k];
        out[BB * NAD + b] = t;
    }
}

// =================== launch ===================
static inline int gs(long long n) { return (int)((n + 255) / 256); }

extern "C" void kernel_launch(void* const* d_in, const int* in_sizes, int n_in,
                              void* d_out, int out_size) {
    const float* obs   = (const float*)d_in[0];
    const float* nf    = (const float*)d_in[1];
    const int*   ei    = (const int*)  d_in[2];
    const int*   batch = (const int*)  d_in[3];
    const float* W0 = (const float*)d_in[4];
    const float* as0 = (const float*)d_in[5];
    const float* ad0 = (const float*)d_in[6];
    const float* b0  = (const float*)d_in[7];
    const float* W1 = (const float*)d_in[8];
    const float* as1 = (const float*)d_in[9];
    const float* ad1 = (const float*)d_in[10];
    const float* b1  = (const float*)d_in[11];
    const float* W2 = (const float*)d_in[12];
    const float* as2 = (const float*)d_in[13];
    const float* ad2 = (const float*)d_in[14];
    const float* b2  = (const float*)d_in[15];
    const float* Ws1 = (const float*)d_in[16];
    const float* bs1 = (const float*)d_in[17];
    const float* lng = (const float*)d_in[18];
    const float* lnb = (const float*)d_in[19];
    const float* Ws2 = (const float*)d_in[20];
    const float* bs2 = (const float*)d_in[21];
    const float* Wa  = (const float*)d_in[22];
    const float* ba  = (const float*)d_in[23];
    const float* Wc  = (const float*)d_in[24];
    const float* bc  = (const float*)d_in[25];
    float* out = (float*)d_out;

    void *pA_s, *pA_d, *pA_e, *pB_s, *pB_d, *pB_e, *p_wf1, *p_wf2;
    cudaGetSymbolAddress(&pA_s, g_as_a);
    cudaGetSymbolAddress(&pA_d, g_ad_a);
    cudaGetSymbolAddress(&pA_e, g_es_a);
    cudaGetSymbolAddress(&pB_s, g_as_b);
    cudaGetSymbolAddress(&pB_d, g_ad_b);
    cudaGetSymbolAddress(&pB_e, g_es_b);
    cudaGetSymbolAddress(&p_wf1, g_wf1);
    cudaGetSymbolAddress(&p_wf2, g_wf2);

    const int AGGB = (NN + 7) / 8;  // 6250

    // 1. init: folds + zero deg/pool/cnt
    k_init<<<160, 256>>>(W0, as0, ad0, W1, as1, ad1, W2, as2, ad2);
    // 2-3. CSR histogram + scan
    k_hist<<<gs(EE / 4), 256>>>(ei);
    k_scan<<<1, 1024>>>();
    // 4. fused CSR fill + layer-0 GEMM (+alpha0)
    k_fillg0<<<2 * G0B, 256>>>(ei, nf, W0);
    // 5. layer-0 aggregate (+alpha1)
    k_agg<128, 2, true, 4, false><<<AGGB, 256>>>(b0,
        (const float*)pA_s, (const float*)pA_d, (const float*)pA_e,
        (float*)pB_s, (float*)pB_d, (float*)pB_e, (const float*)p_wf1, nullptr);
    // 6-7. layer 1
    k_gemm128<128><<<782, 256>>>(W1);
    k_agg<128, 2, true, 2, false><<<AGGB, 256>>>(b1,
        (const float*)pB_s, (const float*)pB_d, (const float*)pB_e,
        (float*)pA_s, (float*)pA_d, (float*)pA_e, (const float*)p_wf2, nullptr);
    // 8-9. layer 2 (agg fuses mean-pool accumulation)
    k_gemm128<64><<<782, 256>>>(W2);
    k_agg<64, 1, false, 0, true><<<AGGB, 256>>>(b2,
        (const float*)pA_s, (const float*)pA_d, (const float*)pA_e,
        nullptr, nullptr, nullptr, nullptr, batch);
    // 10. MLP head
    k_mlp<<<BB, MHD>>>(obs, Ws1, bs1, lng, lnb, Ws2, bs2, Wa, ba, Wc, bc, out);
}

// round 10
// speedup vs baseline: 1.0865x; 1.0865x over previous
#include <cuda_runtime.h>
#include <cuda_bf16.h>
#include <math.h>

#define NN 50000
#define EE 800000
#define BB 64
#define OBSD 128
#define MHD 256
#define NAD 16

// ---------------- scratch ----------------
__device__ float          g_x[NN * 128];
__device__ __nv_bfloat16  g_h[NN * 128];
__device__ float g_as[NN * 2];
__device__ float g_ad[NN * 2];
__device__ int   g_deg[NN + 1];
__device__ int   g_off[NN + 1];
__device__ int   g_cur[NN];
__device__ int   g_csr[EE];
__device__ float g_pool[BB * 64];
__device__ float g_cnt[BB];

__device__ __forceinline__ float lrelu(float v) { return v > 0.f ? v : 0.2f * v; }

__device__ __forceinline__ void red4(float* p, float a, float b, float c, float d) {
    asm volatile("red.global.add.v4.f32 [%0], {%1,%2,%3,%4};"
                 :: "l"(p), "f"(a), "f"(b), "f"(c), "f"(d) : "memory");
}

// bf16 helpers
__device__ __forceinline__ void st_h4(__nv_bfloat16* p, const float* f) {
    uint2 u;
    *reinterpret_cast<__nv_bfloat162*>(&u.x) = __floats2bfloat162_rn(f[0], f[1]);
    *reinterpret_cast<__nv_bfloat162*>(&u.y) = __floats2bfloat162_rn(f[2], f[3]);
    *reinterpret_cast<uint2*>(p) = u;
}
__device__ __forceinline__ void st_h2(__nv_bfloat16* p, const float* f) {
    unsigned u;
    *reinterpret_cast<__nv_bfloat162*>(&u) = __floats2bfloat162_rn(f[0], f[1]);
    *reinterpret_cast<unsigned*>(p) = u;
}
__device__ __forceinline__ void acc_h4(float* acc, unsigned ux, unsigned uy, float w) {
    float2 lo = __bfloat1622float2(*reinterpret_cast<__nv_bfloat162*>(&ux));
    float2 hi = __bfloat1622float2(*reinterpret_cast<__nv_bfloat162*>(&uy));
    acc[0] += w * lo.x; acc[1] += w * lo.y; acc[2] += w * hi.x; acc[3] += w * hi.y;
}
__device__ __forceinline__ void acc_h2(float* acc, unsigned u, float w) {
    float2 lo = __bfloat1622float2(*reinterpret_cast<__nv_bfloat162*>(&u));
    acc[0] += w * lo.x; acc[1] += w * lo.y;
}

// =================== CSR build ===================
__global__ void k_hist(const int* __restrict__ ei) {
    const int4* d4 = reinterpret_cast<const int4*>(ei + EE);
    for (int i = blockIdx.x * blockDim.x + threadIdx.x; i < EE / 4; i += gridDim.x * blockDim.x) {
        int4 v = d4[i];
        atomicAdd(&g_deg[v.x], 1);
        atomicAdd(&g_deg[v.y], 1);
        atomicAdd(&g_deg[v.z], 1);
        atomicAdd(&g_deg[v.w], 1);
    }
}
__global__ void k_scan() {
    __shared__ int sh[1024];
    const int PER = 49;
    int tid = threadIdx.x;
    int base = tid * PER;
    int s = 0;
    for (int k = 0; k < PER; k++) {
        int i = base + k;
        if (i < NN) s += g_deg[i];
    }
    sh[tid] = s;
    __syncthreads();
    for (int o = 1; o < 1024; o <<= 1) {
        int t = (tid >= o) ? sh[tid - o] : 0;
        __syncthreads();
        sh[tid] += t;
        __syncthreads();
    }
    int run = sh[tid] - s;
    for (int k = 0; k < PER; k++) {
        int i = base + k;
        if (i < NN) {
            int d = g_deg[i];
            g_off[i] = run;
            g_cur[i] = run;
            run += d;
        }
    }
    if (tid == 0) g_off[NN] = EE;
}
__global__ void k_fill(const int* __restrict__ ei) {
    const int4* s4 = reinterpret_cast<const int4*>(ei);
    const int4* d4 = reinterpret_cast<const int4*>(ei + EE);
    for (int i = blockIdx.x * blockDim.x + threadIdx.x; i < EE / 4; i += gridDim.x * blockDim.x) {
        int4 s = s4[i];
        int4 d = d4[i];
        g_csr[atomicAdd(&g_cur[d.x], 1)] = s.x;
        g_csr[atomicAdd(&g_cur[d.y], 1)] = s.y;
        g_csr[atomicAdd(&g_cur[d.z], 1)] = s.z;
        g_csr[atomicAdd(&g_cur[d.w], 1)] = s.w;
    }
}

// =================== epilogue helper: alpha dots (layer 1/2 GEMM) ===================
template <int H, int VEC>
__device__ __forceinline__ void alpha_epilogue(int node, int lane, int head,
                                               const float* acc, const float* asv, const float* adv) {
    float vs = 0.f, vd = 0.f;
#pragma unroll
    for (int v = 0; v < VEC; v++) { vs += acc[v] * asv[v]; vd += acc[v] * adv[v]; }
    constexpr int RO = (H == 2) ? 8 : 16;
#pragma unroll
    for (int o = RO; o > 0; o >>= 1) {
        vs += __shfl_down_sync(0xffffffffu, vs, o);
        vd += __shfl_down_sync(0xffffffffu, vd, o);
    }
    if ((lane & ((H == 2) ? 15 : 31)) == 0) {
        g_as[node * H + head] = vs;
        g_ad[node * H + head] = vd;
    }
}

// =================== layer-0 GEMM (FIN=8 -> HC=128) with in-block fold ===================
__global__ void k_gemm0(const float* __restrict__ xin, const float* __restrict__ W,
                        const float* __restrict__ asrc, const float* __restrict__ adst) {
    __shared__ float Wsh[8 * 128];
    __shared__ float wfsh[32];     // [a][k]: a in {as_h0, as_h1, ad_h0, ad_h1}, k in 0..7
    int tid = threadIdx.x, lane = tid & 31, wp = tid >> 5;
    for (int i = tid; i < 8 * 128; i += 256) Wsh[i] = W[i];
    __syncthreads();
    if (tid < 32) {
        int a = tid >> 3, k = tid & 7, h = a & 1;
        const float* av = ((a < 2) ? asrc : adst) + h * 64;
        const float* wr = &Wsh[k * 128 + h * 64];
        float s = 0.f;
#pragma unroll
        for (int c = 0; c < 64; c++) s += wr[c] * av[c];
        wfsh[a * 8 + k] = s;
    }
    __syncthreads();

    for (int node = blockIdx.x * 8 + wp; node < NN; node += gridDim.x * 8) {
        float4 xa = *reinterpret_cast<const float4*>(&xin[node * 8]);
        float4 xb = *reinterpret_cast<const float4*>(&xin[node * 8 + 4]);
        float xk[8] = {xa.x, xa.y, xa.z, xa.w, xb.x, xb.y, xb.z, xb.w};
        float acc[4] = {0.f, 0.f, 0.f, 0.f};
#pragma unroll
        for (int k = 0; k < 8; k++) {
            float4 w = *reinterpret_cast<const float4*>(&Wsh[k * 128 + lane * 4]);
            acc[0] += xk[k] * w.x; acc[1] += xk[k] * w.y;
            acc[2] += xk[k] * w.z; acc[3] += xk[k] * w.w;
        }
        st_h4(&g_h[(size_t)node * 128 + lane * 4], acc);

        // alpha: lane a (a = lane&3) computes dot(x, wfsh[a]); no warp reduction needed
        int a = lane & 3;
        float s = 0.f;
#pragma unroll
        for (int k = 0; k < 8; k++) s += xk[k] * wfsh[a * 8 + k];
        if (lane < 2)      g_as[node * 2 + lane] = s;
        else if (lane < 4) g_ad[node * 2 + lane - 2] = s;
    }
}

// =================== big GEMM (FIN=128 -> HC, H) — R6-proven fp32 version ===================
template <int HC, int H>
__global__ void k_gemm128(const float* __restrict__ W,
                          const float* __restrict__ asrc, const float* __restrict__ adst) {
    constexpr int VEC = HC / 32;
    constexpr int KT = 32;
    constexpr int NCH = 64;
    __shared__ float Wsh[KT * HC];
    __shared__ float xsh[NCH * KT];
    int tid = threadIdx.x, lane = tid & 31, wp = tid >> 5;   // 8 warps
    int head = (H == 2) ? (lane >> 4) : 0;
    float asv[VEC], adv[VEC];
#pragma unroll
    for (int v = 0; v < VEC; v++) { asv[v] = asrc[lane * VEC + v]; adv[v] = adst[lane * VEC + v]; }

    for (int base = blockIdx.x * NCH; base < NN; base += gridDim.x * NCH) {
        float acc[8][VEC];
#pragma unroll
        for (int n = 0; n < 8; n++)
#pragma unroll
            for (int v = 0; v < VEC; v++) acc[n][v] = 0.f;

        for (int k0 = 0; k0 < 128; k0 += KT) {
            for (int i = tid; i < KT * HC; i += 256)
                Wsh[i] = W[((i / HC) + k0) * HC + (i % HC)];
            for (int i = tid; i < NCH * KT; i += 256) {
                int n = base + i / KT;
                xsh[i] = (n < NN) ? g_x[(size_t)n * 128 + k0 + (i % KT)] : 0.f;
            }
            __syncthreads();
#pragma unroll
            for (int kk = 0; kk < KT; kk += 4) {
                float wv[4][VEC];
#pragma unroll
                for (int j = 0; j < 4; j++)
#pragma unroll
                    for (int v = 0; v < VEC; v++)
                        wv[j][v] = Wsh[(kk + j) * HC + lane * VEC + v];
#pragma unroll
                for (int n = 0; n < 8; n++) {
                    float4 xv = *reinterpret_cast<const float4*>(&xsh[(wp * 8 + n) * KT + kk]);
#pragma unroll
                    for (int v = 0; v < VEC; v++)
                        acc[n][v] += xv.x * wv[0][v] + xv.y * wv[1][v]
                                   + xv.z * wv[2][v] + xv.w * wv[3][v];
                }
            }
            __syncthreads();
        }

#pragma unroll
        for (int n = 0; n < 8; n++) {
            int node = base + wp * 8 + n;
            if (node >= NN) break;
            if (VEC == 4) st_h4(&g_h[(size_t)node * HC + lane * 4], acc[n]);
            else          st_h2(&g_h[(size_t)node * HC + lane * 2], acc[n]);
            alpha_epilogue<H, VEC>(node, lane, head, acc[n], asv, adv);
        }
    }
}

// =================== fused softmax-aggregate (warp per dst node, high-MLP gather) ===================
template <int HC, int H, bool ACT>
__global__ void __launch_bounds__(256) k_agg(const float* __restrict__ bias) {
    constexpr int VEC = HC / 32;
    __shared__ int   s_s[8][32];
    __shared__ float s_w[8][32 * H];
    int lane = threadIdx.x & 31, wp = threadIdx.x >> 5;
    int node = blockIdx.x * 8 + wp;
    if (node >= NN) return;
    int head = (H == 2) ? (lane >> 4) : 0;

    float ad0 = g_ad[node * H];
    float ad1 = (H == 2) ? g_ad[node * H + 1] : 0.f;
    int beg = g_off[node], end = g_off[node + 1];

    float acc[VEC];
#pragma unroll
    for (int v = 0; v < VEC; v++) acc[v] = 0.f;
    float d0 = 0.f, d1 = 0.f;

    const __nv_bfloat16* __restrict__ hbase = g_h;

    for (int chunk = beg; chunk < end; chunk += 32) {
        int i = chunk + lane;
        if (i < end) {
            int s = g_csr[i];
            s_s[wp][lane] = s;
            if (H == 2) {
                float2 a = *reinterpret_cast<const float2*>(&g_as[s * 2]);
                float w0 = expf(lrelu(a.x + ad0));
                float w1 = expf(lrelu(a.y + ad1));
                d0 += w0; d1 += w1;
                s_w[wp][lane * 2]     = w0;
                s_w[wp][lane * 2 + 1] = w1;
            } else {
                float w0 = expf(lrelu(g_as[s] + ad0));
                d0 += w0;
                s_w[wp][lane] = w0;
            }
        }
        __syncwarp();
        int cnt = min(32, end - chunk);
        int j = 0;
        for (; j + 8 <= cnt; j += 8) {
            int   ss[8];
            float ww[8];
#pragma unroll
            for (int u = 0; u < 8; u++) {
                ss[u] = s_s[wp][j + u];
                ww[u] = (H == 2) ? s_w[wp][(j + u) * 2 + head] : s_w[wp][j + u];
            }
            if (VEC == 4) {
                uint2 hv[8];
#pragma unroll
                for (int u = 0; u < 8; u++)
                    hv[u] = *reinterpret_cast<const uint2*>(&hbase[(size_t)ss[u] * HC + lane * 4]);
#pragma unroll
                for (int u = 0; u < 8; u++) acc_h4(acc, hv[u].x, hv[u].y, ww[u]);
            } else {
                unsigned hv[8];
#pragma unroll
                for (int u = 0; u < 8; u++)
                    hv[u] = *reinterpret_cast<const unsigned*>(&hbase[(size_t)ss[u] * HC + lane * 2]);
#pragma unroll
                for (int u = 0; u < 8; u++) acc_h2(acc, hv[u], ww[u]);
            }
        }
        for (; j + 4 <= cnt; j += 4) {
            int   ss[4];
            float ww[4];
#pragma unroll
            for (int u = 0; u < 4; u++) {
                ss[u] = s_s[wp][j + u];
                ww[u] = (H == 2) ? s_w[wp][(j + u) * 2 + head] : s_w[wp][j + u];
            }
            if (VEC == 4) {
                uint2 hv[4];
#pragma unroll
                for (int u = 0; u < 4; u++)
                    hv[u] = *reinterpret_cast<const uint2*>(&hbase[(size_t)ss[u] * HC + lane * 4]);
#pragma unroll
                for (int u = 0; u < 4; u++) acc_h4(acc, hv[u].x, hv[u].y, ww[u]);
            } else {
                unsigned hv[4];
#pragma unroll
                for (int u = 0; u < 4; u++)
                    hv[u] = *reinterpret_cast<const unsigned*>(&hbase[(size_t)ss[u] * HC + lane * 2]);
#pragma unroll
                for (int u = 0; u < 4; u++) acc_h2(acc, hv[u], ww[u]);
            }
        }
        for (; j < cnt; j++) {
            int s   = s_s[wp][j];
            float w = (H == 2) ? s_w[wp][j * 2 + head] : s_w[wp][j];
            if (VEC == 4) {
                uint2 hv = *reinterpret_cast<const uint2*>(&hbase[(size_t)s * HC + lane * 4]);
                acc_h4(acc, hv.x, hv.y, w);
            } else {
                unsigned hv = *reinterpret_cast<const unsigned*>(&hbase[(size_t)s * HC + lane * 2]);
                acc_h2(acc, hv, w);
            }
        }
        __syncwarp();
    }

    // self loop: weight recomputed from alpha buffers (g_es removed)
    float ws = expf(lrelu(g_as[node * H + head] + ((H == 2 && head) ? ad1 : ad0)));
    if (VEC == 4) {
        uint2 hv = *reinterpret_cast<const uint2*>(&hbase[(size_t)node * HC + lane * 4]);
        acc_h4(acc, hv.x, hv.y, ws);
    } else {
        unsigned hv = *reinterpret_cast<const unsigned*>(&hbase[(size_t)node * HC + lane * 2]);
        acc_h2(acc, hv, ws);
    }

#pragma unroll
    for (int o = 16; o > 0; o >>= 1) {
        d0 += __shfl_xor_sync(0xffffffffu, d0, o);
        if (H == 2) d1 += __shfl_xor_sync(0xffffffffu, d1, o);
    }
    float dh = (H == 2 && head) ? d1 : d0;
    float inv = 1.0f / (dh + ws + 1e-16f);

    float outv[VEC];
#pragma unroll
    for (int v = 0; v < VEC; v++) {
        float t = acc[v] * inv + bias[lane * VEC + v];
        if (ACT) t = t > 0.f ? t : expm1f(t);
        outv[v] = t;
    }
    if (VEC == 4)
        *reinterpret_cast<float4*>(&g_x[(size_t)node * HC + lane * 4]) =
            make_float4(outv[0], outv[1], outv[2], outv[3]);
    else
        *reinterpret_cast<float2*>(&g_x[(size_t)node * HC + lane * 2]) =
            make_float2(outv[0], outv[1]);
}

// =================== pooling (run-aggregated; batch is sorted) ===================
__global__ void k_pool(const int* __restrict__ batch) {
    int t = blockIdx.x * blockDim.x + threadIdx.x;
    if (t >= (NN / 16) * 16) return;
    int q  = t & 15;
    int nb = t >> 4;
    int n0 = nb * 16;

    float4 accv = make_float4(0.f, 0.f, 0.f, 0.f);
    float cnt = 0.f;
    int curb = batch[n0];
#pragma unroll 4
    for (int k = 0; k < 16; k++) {
        int n = n0 + k;
        int b = batch[n];
        if (b != curb) {
            red4(g_pool + curb * 64 + q * 4, accv.x, accv.y, accv.z, accv.w);
            if (q == 0) atomicAdd(&g_cnt[curb], cnt);
            accv = make_float4(0.f, 0.f, 0.f, 0.f);
            cnt = 0.f;
            curb = b;
        }
        float4 v = *reinterpret_cast<const float4*>(g_x + (size_t)n * 64 + q * 4);
        accv.x += v.x; accv.y += v.y; accv.z += v.z; accv.w += v.w;
        cnt += 1.f;
    }
    red4(g_pool + curb * 64 + q * 4, accv.x, accv.y, accv.z, accv.w);
    if (q == 0) atomicAdd(&g_cnt[curb], cnt);
}

// =================== MLP head ===================
__global__ void k_mlp(const float* __restrict__ obs,
                      const float* __restrict__ Ws1, const float* __restrict__ bs1,
                      const float* __restrict__ lng, const float* __restrict__ lnb,
                      const float* __restrict__ Ws2, const float* __restrict__ bs2,
                      const float* __restrict__ Wa,  const float* __restrict__ ba,
                      const float* __restrict__ Wc,  const float* __restrict__ bc,
                      float* __restrict__ out) {
    __shared__ float comb[64 + OBSD];
    __shared__ float hb[MHD];
    __shared__ float h2[MHD];
    __shared__ float rb[8];
    __shared__ float stats[2];

    int b = blockIdx.x;
    int tid = threadIdx.x;

    if (tid < 64)             comb[tid] = g_pool[b * 64 + tid] / fmaxf(g_cnt[b], 1.0f);
    else if (tid < 64 + OBSD) comb[tid] = obs[b * OBSD + (tid - 64)];
    __syncthreads();

    float s = bs1[tid];
    for (int k = 0; k < 64 + OBSD; k++) s += comb[k] * Ws1[k * MHD + tid];

    float v = s;
#pragma unroll
    for (int o = 16; o > 0; o >>= 1) v += __shfl_down_sync(0xffffffffu, v, o);
    if ((tid & 31) == 0) rb[tid >> 5] = v;
    __syncthreads();
    if (tid == 0) { float t = 0.f; for (int w = 0; w < 8; w++) t += rb[w]; stats[0] = t / MHD; }
    __syncthreads();
    float mu = stats[0];
    float dv = s - mu;
    v = dv * dv;
#pragma unroll
    for (int o = 16; o > 0; o >>= 1) v += __shfl_down_sync(0xffffffffu, v, o);
    if ((tid & 31) == 0) rb[tid >> 5] = v;
    __syncthreads();
    if (tid == 0) { float t = 0.f; for (int w = 0; w < 8; w++) t += rb[w]; stats[1] = t / MHD; }
    __syncthreads();

    float hn = dv * rsqrtf(stats[1] + 1e-5f) * lng[tid] + lnb[tid];
    hb[tid] = fmaxf(hn, 0.f);
    __syncthreads();

    float s2 = bs2[tid];
    for (int k = 0; k < MHD; k++) s2 += hb[k] * Ws2[k * MHD + tid];
    h2[tid] = fmaxf(s2, 0.f);
    __syncthreads();

    if (tid < NAD) {
        float t = ba[tid];
        for (int k = 0; k < MHD; k++) t += h2[k] * Wa[k * NAD + tid];
        out[b * NAD + tid] = t;
    }
    if (tid == NAD) {
        float t = bc[0];
        for (int k = 0; k < MHD; k++) t += h2[k] * Wc[k];
        out[BB * NAD + b] = t;
    }
}

// =================== launch ===================
static inline int gs(long long n) { return (int)((n + 255) / 256); }

extern "C" void kernel_launch(void* const* d_in, const int* in_sizes, int n_in,
                              void* d_out, int out_size) {
    const float* obs   = (const float*)d_in[0];
    const float* nf    = (const float*)d_in[1];
    const int*   ei    = (const int*)  d_in[2];
    const int*   batch = (const int*)  d_in[3];
    const float* W0 = (const float*)d_in[4];
    const float* as0 = (const float*)d_in[5];
    const float* ad0 = (const float*)d_in[6];
    const float* b0  = (const float*)d_in[7];
    const float* W1 = (const float*)d_in[8];
    const float* as1 = (const float*)d_in[9];
    const float* ad1 = (const float*)d_in[10];
    const float* b1  = (const float*)d_in[11];
    const float* W2 = (const float*)d_in[12];
    const float* as2 = (const float*)d_in[13];
    const float* ad2 = (const float*)d_in[14];
    const float* b2  = (const float*)d_in[15];
    const float* Ws1 = (const float*)d_in[16];
    const float* bs1 = (const float*)d_in[17];
    const float* lng = (const float*)d_in[18];
    const float* lnb = (const float*)d_in[19];
    const float* Ws2 = (const float*)d_in[20];
    const float* bs2 = (const float*)d_in[21];
    const float* Wa  = (const float*)d_in[22];
    const float* ba  = (const float*)d_in[23];
    const float* Wc  = (const float*)d_in[24];
    const float* bc  = (const float*)d_in[25];
    float* out = (float*)d_out;

    // zero scratch via memset (no kernel-launch latency floor)
    void *p_deg, *p_pool, *p_cnt;
    cudaGetSymbolAddress(&p_deg,  g_deg);
    cudaGetSymbolAddress(&p_pool, g_pool);
    cudaGetSymbolAddress(&p_cnt,  g_cnt);
    cudaMemsetAsync(p_deg,  0, (NN + 1) * sizeof(int));
    cudaMemsetAsync(p_pool, 0, BB * 64 * sizeof(float));
    cudaMemsetAsync(p_cnt,  0, BB * sizeof(float));

    // ---- CSR build (shared by all 3 layers) ----
    k_hist<<<gs(EE / 4), 256>>>(ei);
    k_scan<<<1, 1024>>>();
    k_fill<<<gs(EE / 4), 256>>>(ei);

    const int AGGB = (NN + 7) / 8;  // 6250

    // ---- layer 0: FIN=8 -> H=2,C=64, ELU ----
    k_gemm0<<<782, 256>>>(nf, W0, as0, ad0);
    k_agg<128, 2, true><<<AGGB, 256>>>(b0);

    // ---- layer 1: 128 -> H=2,C=64, ELU ----
    k_gemm128<128, 2><<<782, 256>>>(W1, as1, ad1);
    k_agg<128, 2, true><<<AGGB, 256>>>(b1);

    // ---- layer 2: 128 -> H=1,C=64 ----
    k_gemm128<64, 1><<<782, 256>>>(W2, as2, ad2);
    k_agg<64, 1, false><<<AGGB, 256>>>(b2);

    // ---- pool + MLP ----
    k_pool<<<gs(NN), 256>>>(batch);
    k_mlp<<<BB, MHD>>>(obs, Ws1, bs1, lng, lnb, Ws2, bs2, Wa, ba, Wc, bc, out);
}